// round 15
// baseline (speedup 1.0000x reference)
#include <cuda_runtime.h>
#include <cuda_bf16.h>
#include <cstdint>

// Embedding gather: out[i, :] = embeddings[x[i], :]
// x: int32 [8192], embeddings: fp32 [32000, 1024], out: fp32 [8192, 1024]
//
// Register-free MLP: cp.async (LDGSTS) gathers land in SMEM with zero data
// registers -> MLP=8 per thread at ~20 regs and near-full occupancy
// (smem-limited to ~6 CTAs/SM). Stores via cp.async.bulk SMEM->GMEM, also
// register-free. 8 rows/CTA, 1024 CTAs x 256 threads.

static constexpr int EMBED_DIM    = 1024;
static constexpr int ROW_BYTES    = EMBED_DIM * 4;     // 4096
static constexpr int ROWS_PER_CTA = 8;
static constexpr int THREADS      = 256;
static constexpr int TILE_BYTES   = ROWS_PER_CTA * ROW_BYTES;  // 32 KB

static __device__ __forceinline__ uint32_t s2u(const void* p) {
    return (uint32_t)__cvta_generic_to_shared(p);
}

// 16B global->shared async copy, L1-bypass (.cg)
static __device__ __forceinline__ void cp16(uint32_t dst_smem, const void* src) {
    asm volatile("cp.async.cg.shared.global [%0], [%1], 16;"
                 :: "r"(dst_smem), "l"(src) : "memory");
}

static __device__ __forceinline__ void bulk_s2g(void* dst_gmem, uint32_t src_smem,
                                                uint32_t bytes) {
    asm volatile(
        "cp.async.bulk.global.shared::cta.bulk_group [%0], [%1], %2;"
        :: "l"(dst_gmem), "r"(src_smem), "r"(bytes) : "memory");
}

__global__ __launch_bounds__(THREADS, 6)
void embedding_cpasync_kernel(const int4* __restrict__ idx4,
                              const float* __restrict__ emb,
                              float* __restrict__ out)
{
    __shared__ alignas(128) char tile[TILE_BYTES];

    const unsigned t   = threadIdx.x;
    const unsigned bid = blockIdx.x;

    // 8 indices via two 16B vector loads (broadcast)
    const int4 i0 = idx4[bid * 2 + 0];
    const int4 i1 = idx4[bid * 2 + 1];
    const int  src[ROWS_PER_CTA] = { i0.x, i0.y, i0.z, i0.w,
                                     i1.x, i1.y, i1.z, i1.w };

    const uint32_t smem_base = s2u(tile);
    const char* emb_lane = (const char*)emb + t * 16u;   // thread's 16B slot

    // 8 register-free gathers in flight per thread (2048 per CTA)
#pragma unroll
    for (int r = 0; r < ROWS_PER_CTA; r++) {
        cp16(smem_base + r * ROW_BYTES + t * 16u,
             emb_lane + (size_t)src[r] * ROW_BYTES);
    }
    asm volatile("cp.async.commit_group;" ::: "memory");
    asm volatile("cp.async.wait_group 0;" ::: "memory");
    __syncthreads();

    // Order generic-proxy SMEM writes before async-proxy bulk reads
    asm volatile("fence.proxy.async.shared::cta;" ::: "memory");

    if (t == 0) {
        float* out_row = out + (size_t)bid * ROWS_PER_CTA * EMBED_DIM;
#pragma unroll
        for (int r = 0; r < ROWS_PER_CTA; r++)
            bulk_s2g(out_row + r * EMBED_DIM, smem_base + r * ROW_BYTES, ROW_BYTES);
        asm volatile("cp.async.bulk.commit_group;" ::: "memory");
        asm volatile("cp.async.bulk.wait_group %0;" :: "n"(0) : "memory");
    }
}

extern "C" void kernel_launch(void* const* d_in, const int* in_sizes, int n_in,
                              void* d_out, int out_size)
{
    const int*   x   = (const int*)d_in[0];          // [4, 2048] int32 indices
    const float* emb = (const float*)d_in[1];        // [32000, 1024] fp32
    float*       out = (float*)d_out;                // [4, 2048, 1024] fp32

    const int n_rows = in_sizes[0];                  // 8192
    const int n_cta  = n_rows / ROWS_PER_CTA;        // 1024

    embedding_cpasync_kernel<<<n_cta, THREADS>>>(
        (const int4*)x, emb, out);
}

// round 16
// speedup vs baseline: 1.0293x; 1.0293x over previous
#include <cuda_runtime.h>
#include <cuda_bf16.h>
#include <cstdint>

// Embedding gather: out[i, :] = embeddings[x[i], :]
// x: int32 [8192], embeddings: fp32 [32000, 1024], out: fp32 [8192, 1024]
//
// Winning shape (R13/R14: 4 rows/CTA, 2048 CTAs x 256 threads, full 2048
// threads/SM) upgraded to 256-bit accesses (sm_100a LDG.E.256 / STG.E.256):
// same 64B/thread in flight, HALF the LSU requests and L1tex queue slots.
//   thread t, j in {0,1}:  row = (t>>7) + 2*j,  32B-lane = t & 127
// ld.global.cg (skip L1) + st.global.cs (evict-first), as measured best.

static constexpr int EMBED_DIM    = 1024;
static constexpr int ROW_BYTES    = EMBED_DIM * 4;       // 4096
static constexpr int ROWS_PER_CTA = 4;
static constexpr int LANES_PER_ROW = ROW_BYTES / 32;     // 128 x 32B

struct V8 { float4 a, b; };

static __device__ __forceinline__ V8 ldcg_v8(const void* p) {
    V8 v;
    asm volatile("ld.global.cg.v8.f32 {%0,%1,%2,%3,%4,%5,%6,%7}, [%8];"
                 : "=f"(v.a.x), "=f"(v.a.y), "=f"(v.a.z), "=f"(v.a.w),
                   "=f"(v.b.x), "=f"(v.b.y), "=f"(v.b.z), "=f"(v.b.w)
                 : "l"(p));
    return v;
}

static __device__ __forceinline__ void stcs_v8(void* p, V8 v) {
    asm volatile("st.global.cs.v8.f32 [%0], {%1,%2,%3,%4,%5,%6,%7,%8};"
                 :: "l"(p),
                    "f"(v.a.x), "f"(v.a.y), "f"(v.a.z), "f"(v.a.w),
                    "f"(v.b.x), "f"(v.b.y), "f"(v.b.z), "f"(v.b.w)
                 : "memory");
}

__global__ __launch_bounds__(256, 8)
void embedding_gather_kernel(const int4* __restrict__ idx4,
                             const char* __restrict__ emb,
                             char* __restrict__ out)
{
    const unsigned t = threadIdx.x;

    // 4 indices in one 16B load (broadcast within CTA)
    const int4 i4 = idx4[blockIdx.x];
    const int  src[ROWS_PER_CTA] = { i4.x, i4.y, i4.z, i4.w };

    const unsigned half = t >> 7;            // 0 or 1: which row of the pair
    const unsigned lane = (t & 127) * 32u;   // byte offset of 32B lane in row

    // rows handled by this thread: half, half+2
    const unsigned r0 = half;
    const unsigned r1 = half + 2;

    // 2 independent 32B gathers (64B in flight/thread), L2-only
    V8 v0 = ldcg_v8(emb + (size_t)src[r0] * ROW_BYTES + lane);
    V8 v1 = ldcg_v8(emb + (size_t)src[r1] * ROW_BYTES + lane);

    // 2 coalesced 32B streaming stores
    char* obase = out + (size_t)blockIdx.x * (ROWS_PER_CTA * ROW_BYTES) + lane;
    stcs_v8(obase + (size_t)r0 * ROW_BYTES, v0);
    stcs_v8(obase + (size_t)r1 * ROW_BYTES, v1);
}

extern "C" void kernel_launch(void* const* d_in, const int* in_sizes, int n_in,
                              void* d_out, int out_size)
{
    const int*   x   = (const int*)d_in[0];          // [4, 2048] int32 indices
    const float* emb = (const float*)d_in[1];        // [32000, 1024] fp32
    float*       out = (float*)d_out;                // [4, 2048, 1024] fp32

    const int n_rows = in_sizes[0];                  // 8192
    const int n_cta  = n_rows / ROWS_PER_CTA;        // 2048

    embedding_gather_kernel<<<n_cta, 256>>>(
        (const int4*)x, (const char*)emb, (char*)out);
}

// round 17
// speedup vs baseline: 1.0324x; 1.0029x over previous
#include <cuda_runtime.h>
#include <cuda_bf16.h>
#include <cstdint>

// Embedding gather: out[i, :] = embeddings[x[i], :]
// x: int32 [8192], embeddings: fp32 [32000, 1024], out: fp32 [8192, 1024]
//
// FINAL — fastest of 12 measured variants (10.208us). Sweep covered
// rows/CTA {1,4,8,16}, MLP {1,2,4,8,40-deep-DMA}, paths {LDG, TMA rings,
// cp.async+bulk, LDG+TMA hybrid}, cache policies {default, .cg/.cs,
// L2 evict_last}, widths {128b, 256b}: all within 10.2-12.5us. The op is
// bound by the L2 fabric's fine-grained gather service rate (~6 TB/s of
// combined L2-level flow), path-independent and insensitive to SM-side
// structure once (resident threads x in-flight requests) saturates.
//
// Winning config: 4 rows/CTA, 2048 CTAs x 256 threads, front-batched MLP=4
// 16B gathers, 24 regs -> 8 CTAs/SM (full 2048 threads),
// ld.global.cg (skip L1) + st.global.cs (evict-first), 32-bit offset math,
// indices via one int4 load.

static constexpr int EMBED_DIM    = 1024;
static constexpr int VEC_PER_ROW  = EMBED_DIM / 4;   // 256 float4 per row
static constexpr int ROWS_PER_CTA = 4;

static __device__ __forceinline__ float4 ldcg_f4(const float4* p) {
    float4 v;
    asm volatile("ld.global.cg.v4.f32 {%0,%1,%2,%3}, [%4];"
                 : "=f"(v.x), "=f"(v.y), "=f"(v.z), "=f"(v.w) : "l"(p));
    return v;
}

static __device__ __forceinline__ void stcs_f4(float4* p, float4 v) {
    asm volatile("st.global.cs.v4.f32 [%0], {%1,%2,%3,%4};"
                 :: "l"(p), "f"(v.x), "f"(v.y), "f"(v.z), "f"(v.w) : "memory");
}

__global__ __launch_bounds__(256, 8)
void embedding_gather_kernel(const int4* __restrict__ idx4,
                             const float4* __restrict__ emb,
                             float4* __restrict__ out)
{
    const unsigned t = threadIdx.x;

    // 4 indices in one 16B load (broadcast within CTA)
    const int4 i4 = idx4[blockIdx.x];

    // 32-bit element offsets: max 31999*256 + 255 < 2^31
    const unsigned off0 = (unsigned)i4.x * VEC_PER_ROW + t;
    const unsigned off1 = (unsigned)i4.y * VEC_PER_ROW + t;
    const unsigned off2 = (unsigned)i4.z * VEC_PER_ROW + t;
    const unsigned off3 = (unsigned)i4.w * VEC_PER_ROW + t;

    // 4 independent gathers, front-batched (MLP=4), L2-only
    float4 v0 = ldcg_f4(emb + off0);
    float4 v1 = ldcg_f4(emb + off1);
    float4 v2 = ldcg_f4(emb + off2);
    float4 v3 = ldcg_f4(emb + off3);

    // 4 coalesced streaming stores (out offsets also < 2^31: 8192*256)
    float4* o = out + (unsigned)blockIdx.x * (ROWS_PER_CTA * VEC_PER_ROW) + t;
    stcs_f4(o + 0 * VEC_PER_ROW, v0);
    stcs_f4(o + 1 * VEC_PER_ROW, v1);
    stcs_f4(o + 2 * VEC_PER_ROW, v2);
    stcs_f4(o + 3 * VEC_PER_ROW, v3);
}

extern "C" void kernel_launch(void* const* d_in, const int* in_sizes, int n_in,
                              void* d_out, int out_size)
{
    const int*   x   = (const int*)d_in[0];          // [4, 2048] int32 indices
    const float* emb = (const float*)d_in[1];        // [32000, 1024] fp32
    float*       out = (float*)d_out;                // [4, 2048, 1024] fp32

    const int n_rows = in_sizes[0];                  // 8192
    const int n_cta  = n_rows / ROWS_PER_CTA;        // 2048

    embedding_gather_kernel<<<n_cta, 256>>>(
        (const int4*)x, (const float4*)emb, (float4*)out);
}